// round 15
// baseline (speedup 1.0000x reference)
#include <cuda_runtime.h>

// EMA final-state: y[b,f] = sum_{k=0}^{K-1} 0.5^{k+1} * x[b, T-1-k, f]
// rel_err == 2^-K (deterministic, validated at K=12/16/24):
// K=20 -> ~9.5e-7, 3 orders under the 1e-3 gate.
//
// K-response is non-monotone: K=12 -> ~6.0us, K=24 -> 5.09/5.25/5.38us
// (3x reproduced champion), K=32 -> 6.1us. Probing K=20 to map the left
// shoulder of the optimum. Everything else identical to the champion:
// one thread per output, coalesced scalar loads, sequential-weight FMA
// form, 128 blocks x 256 threads.

static constexpr int B = 64;
static constexpr int T = 2048;
static constexpr int F = 512;
static constexpr int K = 20;

__global__ void ema_tail_kernel(const float* __restrict__ x, float* __restrict__ out) {
    int idx = blockIdx.x * blockDim.x + threadIdx.x;   // 0 .. B*F-1
    int b = idx >> 9;          // / 512
    int f = idx & (F - 1);     // % 512

    // base index of x[b, T-1, f]
    size_t base = ((size_t)b * T + (T - 1)) * F + f;

    float acc = 0.f;
    float w = 0.5f;

    #pragma unroll
    for (int k = 0; k < K; ++k) {
        acc = fmaf(w, x[base - (size_t)k * F], acc);
        w *= 0.5f;
    }

    out[idx] = acc;   // [B, 1, F] row-major == [B*F] floats
}

extern "C" void kernel_launch(void* const* d_in, const int* in_sizes, int n_in,
                              void* d_out, int out_size) {
    const float* x = (const float*)d_in[0];
    float* out = (float*)d_out;

    const int total = B * F;            // 32768 threads
    const int threads = 256;
    const int blocks = total / threads; // 128 blocks
    ema_tail_kernel<<<blocks, threads>>>(x, out);
}